// round 1
// baseline (speedup 1.0000x reference)
#include <cuda_runtime.h>
#include <stdint.h>

// ---------------------------------------------------------------------------
// SeqFCEncoder: out = relu(dropmask(x) @ W1 + b1) @ W2 + b2
//   B=262144, L=50, H=1024, E=256, fp32 everywhere.
// Fully fused: h never touches HBM. Dropout mask = bit-exact threefry2x32
// replication of jax.random.uniform(jax.random.key(42), (B, L)) < 0.2.
// ---------------------------------------------------------------------------

#define B_TOTAL   262144
#define LSEQ      50
#define HDIM      1024
#define EDIM      256
#define TILE_B    64
#define NTHREADS  256
#define HC        128
#define NCHUNK    (HDIM / HC)
#define XS_STRIDE (TILE_B + 2)          // 66: even (8B-aligned pairs) + conflict pad
#define N_ELEMS   (B_TOTAL * LSEQ)      // 13,107,200
#define HALF_N    (N_ELEMS / 2)         // 6,553,600

// JAX >= 0.4.36 defaults jax_threefry_partitionable=True. If rel_err comes
// back ~0.1, flip this to 0 (legacy split-counter scheme).
#define JAX_PARTITIONABLE 1

typedef unsigned long long u64;
typedef unsigned int u32;

// ---- packed f32x2 helpers (SASS FFMA2; only reachable from PTX) ----
__device__ __forceinline__ u64 fma2(u64 a, u64 b, u64 c) {
  u64 d;
  asm("fma.rn.f32x2 %0, %1, %2, %3;" : "=l"(d) : "l"(a), "l"(b), "l"(c));
  return d;
}
__device__ __forceinline__ u64 splat2(float v) {
  u64 r;
  asm("mov.b64 %0, {%1, %2};" : "=l"(r) : "f"(v), "f"(v));
  return r;
}
__device__ __forceinline__ float2 unpack2(u64 v) {
  float2 f;
  asm("mov.b64 {%0, %1}, %2;" : "=f"(f.x), "=f"(f.y) : "l"(v));
  return f;
}

// ---- threefry2x32 with key = (0, 42)  [jax.random.key(42)] ----
__device__ __forceinline__ u32 rotl32(u32 x, u32 r) { return __funnelshift_l(x, x, r); }

__device__ __forceinline__ void tf2x32(u32 x0, u32 x1, u32 &o0, u32 &o1) {
  const u32 ks0 = 0u, ks1 = 42u, ks2 = 0u ^ 42u ^ 0x1BD11BDAu;
  x0 += ks0; x1 += ks1;
#define TFR(r) { x0 += x1; x1 = rotl32(x1, r); x1 ^= x0; }
  TFR(13) TFR(15) TFR(26) TFR(6)
  x0 += ks1; x1 += ks2 + 1u;
  TFR(17) TFR(29) TFR(16) TFR(24)
  x0 += ks2; x1 += ks0 + 2u;
  TFR(13) TFR(15) TFR(26) TFR(6)
  x0 += ks0; x1 += ks1 + 3u;
  TFR(17) TFR(29) TFR(16) TFR(24)
  x0 += ks1; x1 += ks2 + 4u;
  TFR(13) TFR(15) TFR(26) TFR(6)
  x0 += ks2; x1 += ks0 + 5u;
#undef TFR
  o0 = x0; o1 = x1;
}

// drop decision for flat element index i in the (B, L) uniform draw
__device__ __forceinline__ bool drop_elem(u32 i) {
  u32 o0, o1, bits;
#if JAX_PARTITIONABLE
  tf2x32(0u, i, o0, o1);            // counter = u64 flat index: (hi, lo)
  bits = o0 ^ o1;
#else
  if (i < (u32)HALF_N) { tf2x32(i, i + (u32)HALF_N, o0, o1); bits = o0; }
  else                 { tf2x32(i - (u32)HALF_N, i, o0, o1); bits = o1; }
#endif
  // jax uniform: bitcast(bits>>9 | 0x3f800000) - 1.0   (maxval=1, minval=0)
  float u = __uint_as_float((bits >> 9) | 0x3f800000u) - 1.0f;
  return u < 0.2f;
}

__global__ void __launch_bounds__(NTHREADS, 2)
seqfc_kernel(const float* __restrict__ seq,
             const float* __restrict__ W1,
             const float* __restrict__ b1,
             const float* __restrict__ W2,
             const float* __restrict__ b2,
             float* __restrict__ out)
{
  __shared__ __align__(16) float xsT[LSEQ][XS_STRIDE];   // x transposed [l][r]
  __shared__ __align__(16) float hsT[HC][XS_STRIDE];     // h chunk transposed [k][r]
  __shared__ int fneg[TILE_B];

  const int tid  = threadIdx.x;
  const int row0 = blockIdx.x * TILE_B;

  // ---- load + transpose x tile (coalesced gmem reads) ----
  const float* sp = seq + (size_t)row0 * LSEQ;
  for (int idx = tid; idx < TILE_B * LSEQ; idx += NTHREADS) {
    int r = idx / LSEQ;
    int l = idx - r * LSEQ;
    xsT[l][r] = sp[idx];
  }
  __syncthreads();

  // ---- first padding position per row (first exact -1.0, else L) ----
  if (tid < TILE_B) {
    int f = LSEQ;
#pragma unroll
    for (int l = LSEQ - 1; l >= 0; --l)
      if (xsT[l][tid] == -1.0f) f = l;
    fneg[tid] = f;
  }
  __syncthreads();

  // ---- dropout on valid region ----
  for (int idx = tid; idx < TILE_B * LSEQ; idx += NTHREADS) {
    int r = idx / LSEQ;
    int l = idx - r * LSEQ;
    if (l < fneg[r]) {
      u32 gi = (u32)(row0 + r) * (u32)LSEQ + (u32)l;
      if (drop_elem(gi)) xsT[l][r] = 0.0f;
    }
  }
  __syncthreads();

  // ---- fused MLP ----
  const int hcol = tid & 63;          // GEMM1 col (also +64)
  const int rb1  = (tid >> 6) * 16;   // GEMM1 row base (16 rows = 8 pairs)
  const int ec   = (tid & 31) * 8;    // GEMM2 col base (8 cols)
  const int rb2  = (tid >> 5) * 8;    // GEMM2 row base (8 rows = 4 pairs)

  u64 acc[4][8];                      // out accum: row-pair i, col j (lo=even row)
#pragma unroll
  for (int i = 0; i < 4; ++i)
#pragma unroll
    for (int j = 0; j < 8; ++j) acc[i][j] = 0ull;

  for (int c = 0; c < NCHUNK; ++c) {
    const int hbase = c * HC;

    // ---- GEMM1: hsT = relu(x @ W1[:, hbase:hbase+HC] + b1) ----
    {
      u64 a1[8][2];
      const u64 bb0 = splat2(b1[hbase + hcol]);
      const u64 bb1 = splat2(b1[hbase + hcol + 64]);
#pragma unroll
      for (int i = 0; i < 8; ++i) { a1[i][0] = bb0; a1[i][1] = bb1; }

      const float* w1p = W1 + hbase + hcol;
#pragma unroll 2
      for (int k = 0; k < LSEQ; ++k) {
        const u64 w0 = splat2(w1p[(size_t)k * HDIM]);
        const u64 w1v = splat2(w1p[(size_t)k * HDIM + 64]);
#pragma unroll
        for (int i = 0; i < 8; ++i) {
          const u64 xp = *(const u64*)&xsT[k][rb1 + 2 * i];
          a1[i][0] = fma2(xp, w0, a1[i][0]);
          a1[i][1] = fma2(xp, w1v, a1[i][1]);
        }
      }
#pragma unroll
      for (int i = 0; i < 8; ++i) {
        float2 v0 = unpack2(a1[i][0]);
        float2 v1 = unpack2(a1[i][1]);
        hsT[hcol][rb1 + 2 * i]          = fmaxf(v0.x, 0.0f);
        hsT[hcol][rb1 + 2 * i + 1]      = fmaxf(v0.y, 0.0f);
        hsT[hcol + 64][rb1 + 2 * i]     = fmaxf(v1.x, 0.0f);
        hsT[hcol + 64][rb1 + 2 * i + 1] = fmaxf(v1.y, 0.0f);
      }
    }
    __syncthreads();

    // ---- GEMM2: acc += h_chunk @ W2[hbase:hbase+HC, :] ----
    const float* w2p = W2 + (size_t)hbase * EDIM + ec;
#pragma unroll 4
    for (int k = 0; k < HC; ++k) {
      const float4 wa = *(const float4*)(w2p + (size_t)k * EDIM);
      const float4 wb = *(const float4*)(w2p + (size_t)k * EDIM + 4);
      const u64 h0 = *(const u64*)&hsT[k][rb2];
      const u64 h1 = *(const u64*)&hsT[k][rb2 + 2];
      const u64 h2 = *(const u64*)&hsT[k][rb2 + 4];
      const u64 h3 = *(const u64*)&hsT[k][rb2 + 6];
      u64 w[8];
      w[0] = splat2(wa.x); w[1] = splat2(wa.y); w[2] = splat2(wa.z); w[3] = splat2(wa.w);
      w[4] = splat2(wb.x); w[5] = splat2(wb.y); w[6] = splat2(wb.z); w[7] = splat2(wb.w);
#pragma unroll
      for (int j = 0; j < 8; ++j) {
        acc[0][j] = fma2(h0, w[j], acc[0][j]);
        acc[1][j] = fma2(h1, w[j], acc[1][j]);
        acc[2][j] = fma2(h2, w[j], acc[2][j]);
        acc[3][j] = fma2(h3, w[j], acc[3][j]);
      }
    }
    __syncthreads();   // protect hsT before next chunk overwrites it
  }

  // ---- epilogue: + b2, store (vectorized, coalesced) ----
  float bb[8];
#pragma unroll
  for (int j = 0; j < 8; ++j) bb[j] = b2[ec + j];

  float* op = out + (size_t)(row0 + rb2) * EDIM + ec;
#pragma unroll
  for (int i = 0; i < 4; ++i) {
    float2 v[8];
#pragma unroll
    for (int j = 0; j < 8; ++j) v[j] = unpack2(acc[i][j]);
    float4 r0a = make_float4(v[0].x + bb[0], v[1].x + bb[1], v[2].x + bb[2], v[3].x + bb[3]);
    float4 r0b = make_float4(v[4].x + bb[4], v[5].x + bb[5], v[6].x + bb[6], v[7].x + bb[7]);
    float4 r1a = make_float4(v[0].y + bb[0], v[1].y + bb[1], v[2].y + bb[2], v[3].y + bb[3]);
    float4 r1b = make_float4(v[4].y + bb[4], v[5].y + bb[5], v[6].y + bb[6], v[7].y + bb[7]);
    *(float4*)(op + (size_t)(2 * i) * EDIM)         = r0a;
    *(float4*)(op + (size_t)(2 * i) * EDIM + 4)     = r0b;
    *(float4*)(op + (size_t)(2 * i + 1) * EDIM)     = r1a;
    *(float4*)(op + (size_t)(2 * i + 1) * EDIM + 4) = r1b;
  }
}

extern "C" void kernel_launch(void* const* d_in, const int* in_sizes, int n_in,
                              void* d_out, int out_size) {
  (void)in_sizes; (void)n_in; (void)out_size;
  const float* seq = (const float*)d_in[0];
  const float* W1  = (const float*)d_in[1];
  const float* b1  = (const float*)d_in[2];
  const float* W2  = (const float*)d_in[3];
  const float* b2  = (const float*)d_in[4];
  seqfc_kernel<<<B_TOTAL / TILE_B, NTHREADS>>>(seq, W1, b1, W2, b2, (float*)d_out);
}

// round 3
// speedup vs baseline: 2.1441x; 2.1441x over previous
#include <cuda_runtime.h>
#include <cuda_bf16.h>
#include <stdint.h>

// ---------------------------------------------------------------------------
// SeqFCEncoder via warp-level mma.sync (base ISA — tcgen05 rejected by the
// harness's compute_103 PTX target). Split-bf16 3-pass per GEMM:
//   A*B = Ahi*Bhi + Alo*Bhi + Ahi*Blo   (fp32 accum, err ~2^-17)
// out = relu(dropmask(x) @ W1 + b1) @ W2 + b2
// B=262144, L=50, H=1024, E=256. Threefry dropout bit-exact (R1: rel_err 0).
// ---------------------------------------------------------------------------

typedef unsigned int u32;
typedef unsigned long long u64;

#define B_TOTAL   262144
#define LSEQ      50
#define HDIM      1024
#define EDIM      256
#define MTILE     64
#define NTHREADS  256
#define KC        64
#define NCHUNK    (HDIM / KC)     // 16
#define K1PAD     64

// ---- smem layout (bytes, dynamic) ----
#define SM_XHI   0              // 8KB   X hi  [64 m][64 k] SW128
#define SM_XLO   8192           // 8KB
#define SM_HHI   16384          // 8KB   h chunk hi [64 m][64 k] SW128
#define SM_HLO   24576          // 8KB
#define SM_B1    32768          // 4KB
#define SM_B2    36864          // 1KB
#define SM_WBUF  37888          // 2 x 80KB weight buffers (1024-aligned)
#define WBUFSZ   81920
#define W1HI     0              // 8KB  [64 n][64 k] SW128
#define W1LO     8192
#define W2HI     16384          // 32KB [256 n][64 k] SW128
#define W2LO     49152
#define SMEM_TOTAL (SM_WBUF + 2 * WBUFSZ)   // 201728

// ---- pre-split, pre-swizzled weight images (SW128 K-major [n][k=64]) ----
__device__ __align__(1024) unsigned char g_w1img[NCHUNK][2][KC   * K1PAD * 2]; // 256KB
__device__ __align__(1024) unsigned char g_w2img[NCHUNK][2][EDIM * K1PAD * 2]; // 1MB

// ============================ low-level helpers =============================
__device__ __forceinline__ u32 smem_u32_of(const void* p) {
  u32 a;
  asm("{ .reg .u64 t; cvta.to.shared.u64 t, %1; cvt.u32.u64 %0, t; }" : "=r"(a) : "l"(p));
  return a;
}
// byte offset of bf16 element (row r, col k) in a SW128 image with 128B rows
__device__ __forceinline__ u32 swz(int r, int k) {
  u32 off = ((u32)(r >> 3) << 10) | ((u32)(r & 7) << 7) | ((u32)k << 1);
  return off ^ ((off >> 3) & 0x70u);
}
__device__ __forceinline__ void ldsm4(u32 addr, u32 f[4]) {
  asm volatile("ldmatrix.sync.aligned.m8n8.x4.shared.b16 {%0,%1,%2,%3}, [%4];"
               : "=r"(f[0]), "=r"(f[1]), "=r"(f[2]), "=r"(f[3]) : "r"(addr));
}
// A-operand (row-major [m][k]) x4 address for this lane
__device__ __forceinline__ u32 a_addr(u32 img, int m0, int k0, int lr, int lg) {
  return img + swz(m0 + lr + ((lg & 1) << 3), k0 + ((lg >> 1) << 3));
}
// B-operand (row-major [n][k]) x4 address for this lane (non-trans)
__device__ __forceinline__ u32 b_addr(u32 img, int n0, int k0, int lr, int lg) {
  return img + swz(n0 + lr + ((lg >> 1) << 3), k0 + ((lg & 1) << 3));
}
__device__ __forceinline__ void mma16816(float c[4], const u32 a[4], u32 b0, u32 b1) {
  asm volatile(
    "mma.sync.aligned.m16n8k16.row.col.f32.bf16.bf16.f32 "
    "{%0,%1,%2,%3}, {%4,%5,%6,%7}, {%8,%9}, {%0,%1,%2,%3};"
    : "+f"(c[0]), "+f"(c[1]), "+f"(c[2]), "+f"(c[3])
    : "r"(a[0]), "r"(a[1]), "r"(a[2]), "r"(a[3]), "r"(b0), "r"(b1));
}
__device__ __forceinline__ void cpa16(u32 dst, const void* src) {
  asm volatile("cp.async.cg.shared.global [%0], [%1], 16;" :: "r"(dst), "l"(src));
}
#define CP_COMMIT() asm volatile("cp.async.commit_group;" ::: "memory")
#define CP_WAIT0()  asm volatile("cp.async.wait_group 0;" ::: "memory")

// ============================ threefry dropout ==============================
__device__ __forceinline__ u32 rotl32(u32 x, u32 r) { return __funnelshift_l(x, x, r); }
__device__ __forceinline__ void tf2x32(u32 x0, u32 x1, u32 &o0, u32 &o1) {
  const u32 ks0 = 0u, ks1 = 42u, ks2 = 0u ^ 42u ^ 0x1BD11BDAu;
  x0 += ks0; x1 += ks1;
#define TFR(r) { x0 += x1; x1 = rotl32(x1, r); x1 ^= x0; }
  TFR(13) TFR(15) TFR(26) TFR(6)
  x0 += ks1; x1 += ks2 + 1u;
  TFR(17) TFR(29) TFR(16) TFR(24)
  x0 += ks2; x1 += ks0 + 2u;
  TFR(13) TFR(15) TFR(26) TFR(6)
  x0 += ks0; x1 += ks1 + 3u;
  TFR(17) TFR(29) TFR(16) TFR(24)
  x0 += ks1; x1 += ks2 + 4u;
  TFR(13) TFR(15) TFR(26) TFR(6)
  x0 += ks2; x1 += ks0 + 5u;
#undef TFR
  o0 = x0; o1 = x1;
}
__device__ __forceinline__ bool drop_elem(u32 i) {   // validated rel_err 0.0 (R1)
  u32 o0, o1;
  tf2x32(0u, i, o0, o1);
  u32 bits = o0 ^ o1;
  float u = __uint_as_float((bits >> 9) | 0x3f800000u) - 1.0f;
  return u < 0.2f;
}

// ============================ split helpers =================================
__device__ __forceinline__ void split_pack(float a, float b, u32 &h, u32 &l) {
  __nv_bfloat16 ha = __float2bfloat16(a);
  __nv_bfloat16 hb = __float2bfloat16(b);
  __nv_bfloat16 la = __float2bfloat16(a - __bfloat162float(ha));
  __nv_bfloat16 lb = __float2bfloat16(b - __bfloat162float(hb));
  h = (u32)__bfloat16_as_ushort(ha) | ((u32)__bfloat16_as_ushort(hb) << 16);
  l = (u32)__bfloat16_as_ushort(la) | ((u32)__bfloat16_as_ushort(lb) << 16);
}

// ============================ prep kernel ===================================
// W1/W2 -> hi/lo bf16 SW128 images [n][k=64], zero-padded k >= 50 for W1.
__global__ void prep_kernel(const float* __restrict__ W1,
                            const float* __restrict__ W2) {
  int idx = blockIdx.x * blockDim.x + threadIdx.x;
  const int N1 = NCHUNK * KC * K1PAD;
  const int N2 = NCHUNK * EDIM * K1PAD;
  if (idx < N1) {
    int kc = idx / (KC * K1PAD);
    int r  = idx - kc * (KC * K1PAD);
    int n = r / K1PAD, k = r - (r / K1PAD) * K1PAD;
    float w = (k < LSEQ) ? W1[(size_t)k * HDIM + kc * KC + n] : 0.0f;
    __nv_bfloat16 hi = __float2bfloat16(w);
    __nv_bfloat16 lo = __float2bfloat16(w - __bfloat162float(hi));
    u32 sw = swz(n, k);
    *(unsigned short*)&g_w1img[kc][0][sw] = __bfloat16_as_ushort(hi);
    *(unsigned short*)&g_w1img[kc][1][sw] = __bfloat16_as_ushort(lo);
  } else if (idx < N1 + N2) {
    int r2 = idx - N1;
    int kc = r2 / (EDIM * K1PAD);
    int r  = r2 - kc * (EDIM * K1PAD);
    int n = r / K1PAD, k = r - (r / K1PAD) * K1PAD;
    float w = W2[(size_t)(kc * KC + k) * EDIM + n];
    __nv_bfloat16 hi = __float2bfloat16(w);
    __nv_bfloat16 lo = __float2bfloat16(w - __bfloat162float(hi));
    u32 sw = swz(n, k);
    *(unsigned short*)&g_w2img[kc][0][sw] = __bfloat16_as_ushort(hi);
    *(unsigned short*)&g_w2img[kc][1][sw] = __bfloat16_as_ushort(lo);
  }
}

// ============================ main kernel ===================================
extern __shared__ __align__(1024) unsigned char smem_raw[];

__global__ void __launch_bounds__(NTHREADS)
seqfc_main(const float* __restrict__ seq,
           const float* __restrict__ b1,
           const float* __restrict__ b2,
           float* __restrict__ out)
{
  const int tid  = threadIdx.x;
  const int wid  = tid >> 5;
  const int lane = tid & 31;
  const int lr   = lane & 7;          // ldmatrix row-within-group
  const int lg   = lane >> 3;         // ldmatrix group
  const int gid  = lane >> 2;         // mma group id (row)
  const int tig  = lane & 3;          // mma thread-in-group (col pair)
  const int wr   = wid & 3;           // warp row group: rows [wr*16, wr*16+16)
  const int wc   = wid >> 2;          // warp col group
  const int row0 = blockIdx.x * MTILE;

  const u32 sm = smem_u32_of(smem_raw);
  float* b1s = (float*)(smem_raw + SM_B1);
  float* b2s = (float*)(smem_raw + SM_B2);

  // ---- prologue: start weight copy for chunk 0 immediately ----
  {
    u32 d1 = sm + SM_WBUF;
    const unsigned char* s1 = &g_w1img[0][0][0];          // 16KB (hi+lo contiguous)
    for (int i = tid; i < 1024; i += NTHREADS) cpa16(d1 + i * 16, s1 + (size_t)i * 16);
    u32 d2 = sm + SM_WBUF + W2HI;
    const unsigned char* s2 = &g_w2img[0][0][0];          // 64KB
    for (int i = tid; i < 4096; i += NTHREADS) cpa16(d2 + i * 16, s2 + (size_t)i * 16);
    CP_COMMIT();
  }

  // ---- biases ----
  for (int i = tid; i < HDIM; i += NTHREADS) b1s[i] = b1[i];
  for (int i = tid; i < EDIM; i += NTHREADS) b2s[i] = b2[i];

  // ---- X stage: load row, mask, dropout, split, store SW128 image ----
  if (tid < MTILE) {
    const int grow = row0 + tid;
    const float2* xp2 = (const float2*)(seq + (size_t)grow * LSEQ);
    float xv[LSEQ];
#pragma unroll
    for (int i = 0; i < LSEQ / 2; ++i) { float2 t = xp2[i]; xv[2*i] = t.x; xv[2*i+1] = t.y; }
    int f = LSEQ;
#pragma unroll
    for (int l = LSEQ - 1; l >= 0; --l) if (xv[l] == -1.0f) f = l;
    const u32 gbase = (u32)grow * (u32)LSEQ;
#pragma unroll
    for (int l = 0; l < LSEQ; ++l)
      if (l < f && drop_elem(gbase + l)) xv[l] = 0.0f;
#pragma unroll
    for (int c = 0; c < 32; ++c) {
      float a = (2*c   < LSEQ) ? xv[2*c]   : 0.0f;
      float b = (2*c+1 < LSEQ) ? xv[2*c+1] : 0.0f;
      u32 h, l;
      split_pack(a, b, h, l);
      u32 o = swz(tid, 2 * c);
      *(u32*)(smem_raw + SM_XHI + o) = h;
      *(u32*)(smem_raw + SM_XLO + o) = l;
    }
  }
  __syncthreads();

  // ---- X A-fragments (persistent, reused every chunk) ----
  u32 axh[4][4], axl[4][4];
#pragma unroll
  for (int kt = 0; kt < 4; ++kt) {
    ldsm4(a_addr(sm + SM_XHI, wr * 16, kt * 16, lr, lg), axh[kt]);
    ldsm4(a_addr(sm + SM_XLO, wr * 16, kt * 16, lr, lg), axl[kt]);
  }

  // ---- GEMM2 accumulators: warp tile = 16 rows x 128 cols (16 n-tiles) ----
  float acc2[16][4];
#pragma unroll
  for (int i = 0; i < 16; ++i)
#pragma unroll
    for (int j = 0; j < 4; ++j) acc2[i][j] = 0.0f;

  // ---- chunk loop ----
  for (int kc = 0; kc < NCHUNK; ++kc) {
    const u32 wb = sm + SM_WBUF + (u32)(kc & 1) * WBUFSZ;

    CP_WAIT0();
    __syncthreads();          // buffer[kc&1] ready; all warps done with kc-1

    // prefetch next chunk into other buffer (overlaps with compute below)
    if (kc + 1 < NCHUNK) {
      u32 nb = sm + SM_WBUF + (u32)((kc + 1) & 1) * WBUFSZ;
      const unsigned char* s1 = &g_w1img[kc + 1][0][0];
      for (int i = tid; i < 1024; i += NTHREADS) cpa16(nb + i * 16, s1 + (size_t)i * 16);
      const unsigned char* s2 = &g_w2img[kc + 1][0][0];
      for (int i = tid; i < 4096; i += NTHREADS) cpa16(nb + W2HI + i * 16, s2 + (size_t)i * 16);
      CP_COMMIT();
    }

    // ---- GEMM1: h_chunk[64 x 64] = X @ W1chunk (warp: 16 rows x 32 cols) ----
    float acc1[4][4];
#pragma unroll
    for (int i = 0; i < 4; ++i)
#pragma unroll
      for (int j = 0; j < 4; ++j) acc1[i][j] = 0.0f;

#pragma unroll
    for (int kt = 0; kt < 4; ++kt) {
      const int k0 = kt * 16;
#pragma unroll
      for (int ntp = 0; ntp < 2; ++ntp) {
        const int n0 = wc * 32 + ntp * 16;
        u32 bh[4], bl[4];
        ldsm4(b_addr(wb + W1HI, n0, k0, lr, lg), bh);
        ldsm4(b_addr(wb + W1LO, n0, k0, lr, lg), bl);
        mma16816(acc1[2*ntp],     axh[kt], bh[0], bh[1]);
        mma16816(acc1[2*ntp + 1], axh[kt], bh[2], bh[3]);
        mma16816(acc1[2*ntp],     axl[kt], bh[0], bh[1]);
        mma16816(acc1[2*ntp + 1], axl[kt], bh[2], bh[3]);
        mma16816(acc1[2*ntp],     axh[kt], bl[0], bl[1]);
        mma16816(acc1[2*ntp + 1], axh[kt], bl[2], bl[3]);
      }
    }

    // ---- bias + relu + split -> h images ----
    {
      const int r0 = wr * 16 + gid;
#pragma unroll
      for (int nt = 0; nt < 4; ++nt) {
        const int cc = wc * 32 + nt * 8 + 2 * tig;
        const float bb0 = b1s[kc * KC + cc];
        const float bb1 = b1s[kc * KC + cc + 1];
        float v0 = fmaxf(acc1[nt][0] + bb0, 0.0f);
        float v1 = fmaxf(acc1[nt][1] + bb1, 0.0f);
        float v2 = fmaxf(acc1[nt][2] + bb0, 0.0f);
        float v3 = fmaxf(acc1[nt][3] + bb1, 0.0f);
        u32 h0, l0, h1, l1;
        split_pack(v0, v1, h0, l0);
        split_pack(v2, v3, h1, l1);
        u32 oa = swz(r0, cc), ob = swz(r0 + 8, cc);
        *(u32*)(smem_raw + SM_HHI + oa) = h0;
        *(u32*)(smem_raw + SM_HLO + oa) = l0;
        *(u32*)(smem_raw + SM_HHI + ob) = h1;
        *(u32*)(smem_raw + SM_HLO + ob) = l1;
      }
    }
    __syncthreads();          // h visible to all warps

    // ---- GEMM2: acc2 += h_chunk @ W2chunk (warp: 16 rows x 128 cols) ----
#pragma unroll
    for (int kt = 0; kt < 4; ++kt) {
      const int k0 = kt * 16;
      u32 ahh[4], ahl[4];
      ldsm4(a_addr(sm + SM_HHI, wr * 16, k0, lr, lg), ahh);
      ldsm4(a_addr(sm + SM_HLO, wr * 16, k0, lr, lg), ahl);
#pragma unroll
      for (int ntp = 0; ntp < 8; ++ntp) {
        const int n0 = wc * 128 + ntp * 16;
        u32 bh[4], bl[4];
        ldsm4(b_addr(wb + W2HI, n0, k0, lr, lg), bh);
        ldsm4(b_addr(wb + W2LO, n0, k0, lr, lg), bl);
        mma16816(acc2[2*ntp],     ahh, bh[0], bh[1]);
        mma16816(acc2[2*ntp + 1], ahh, bh[2], bh[3]);
        mma16816(acc2[2*ntp],     ahl, bh[0], bh[1]);
        mma16816(acc2[2*ntp + 1], ahl, bh[2], bh[3]);
        mma16816(acc2[2*ntp],     ahh, bl[0], bl[1]);
        mma16816(acc2[2*ntp + 1], ahh, bl[2], bl[3]);
      }
    }
  }

  // ---- epilogue: + b2, store ----
  {
    const int r0 = row0 + wr * 16 + gid;
#pragma unroll
    for (int nt = 0; nt < 16; ++nt) {
      const int c = wc * 128 + nt * 8 + 2 * tig;
      const float bb0 = b2s[c], bb1 = b2s[c + 1];
      float2 va = make_float2(acc2[nt][0] + bb0, acc2[nt][1] + bb1);
      float2 vb = make_float2(acc2[nt][2] + bb0, acc2[nt][3] + bb1);
      *(float2*)(out + (size_t)r0 * EDIM + c)       = va;
      *(float2*)(out + (size_t)(r0 + 8) * EDIM + c) = vb;
    }
  }
}

// ============================ launch ========================================
extern "C" void kernel_launch(void* const* d_in, const int* in_sizes, int n_in,
                              void* d_out, int out_size) {
  (void)in_sizes; (void)n_in; (void)out_size;
  const float* seq = (const float*)d_in[0];
  const float* W1  = (const float*)d_in[1];
  const float* b1  = (const float*)d_in[2];
  const float* W2  = (const float*)d_in[3];
  const float* b2  = (const float*)d_in[4];

  cudaFuncSetAttribute(seqfc_main, cudaFuncAttributeMaxDynamicSharedMemorySize,
                       SMEM_TOTAL);

  const int prep_total = NCHUNK * KC * K1PAD + NCHUNK * EDIM * K1PAD;
  prep_kernel<<<(prep_total + 255) / 256, 256>>>(W1, W2);
  seqfc_main<<<B_TOTAL / MTILE, NTHREADS, SMEM_TOTAL>>>(seq, b1, b2, (float*)d_out);
}

// round 4
// speedup vs baseline: 2.4738x; 1.1538x over previous
#include <cuda_runtime.h>
#include <cuda_bf16.h>
#include <stdint.h>

// ---------------------------------------------------------------------------
// SeqFCEncoder via warp-level mma.sync (compute_103 base ISA).
// Split-bf16 3-pass per GEMM: A*B = Ahi*Bhi + Alo*Bhi + Ahi*Blo (fp32 accum).
// R4: MTILE 64->128, 512 threads (16 warps), halved weight L2 traffic,
//     W1 single-buffered / W2 double-buffered to fit 213KB smem.
// ---------------------------------------------------------------------------

typedef unsigned int u32;
typedef unsigned long long u64;

#define B_TOTAL   262144
#define LSEQ      50
#define HDIM      1024
#define EDIM      256
#define MTILE     128
#define NTHREADS  512
#define KC        64
#define NCHUNK    (HDIM / KC)     // 16
#define K1PAD     64

// ---- smem layout (bytes, dynamic) ----
#define SM_XHI   0               // 16KB  X hi  [128 m][64 k] SW128
#define SM_XLO   16384           // 16KB
#define SM_HHI   32768           // 16KB  h chunk hi [128 m][64 k] SW128
#define SM_HLO   49152           // 16KB
#define SM_B1    65536           // 4KB
#define SM_B2    69632           // 1KB
#define SM_W1    70656           // 16KB single buffer [hi 8K | lo 8K]
#define SM_W2    87040           // 2 x 64KB double buffer [hi 32K | lo 32K]
#define W2BUFSZ  65536
#define SMEM_TOTAL (SM_W2 + 2 * W2BUFSZ)   // 218112

// ---- pre-split, pre-swizzled weight images (SW128 K-major [n][k=64]) ----
__device__ __align__(1024) unsigned char g_w1img[NCHUNK][2][KC   * K1PAD * 2]; // 256KB
__device__ __align__(1024) unsigned char g_w2img[NCHUNK][2][EDIM * K1PAD * 2]; // 1MB

// ============================ low-level helpers =============================
__device__ __forceinline__ u32 smem_u32_of(const void* p) {
  u32 a;
  asm("{ .reg .u64 t; cvta.to.shared.u64 t, %1; cvt.u32.u64 %0, t; }" : "=r"(a) : "l"(p));
  return a;
}
__device__ __forceinline__ u32 swz(int r, int k) {
  u32 off = ((u32)(r >> 3) << 10) | ((u32)(r & 7) << 7) | ((u32)k << 1);
  return off ^ ((off >> 3) & 0x70u);
}
__device__ __forceinline__ void ldsm4(u32 addr, u32 f[4]) {
  asm volatile("ldmatrix.sync.aligned.m8n8.x4.shared.b16 {%0,%1,%2,%3}, [%4];"
               : "=r"(f[0]), "=r"(f[1]), "=r"(f[2]), "=r"(f[3]) : "r"(addr));
}
__device__ __forceinline__ u32 a_addr(u32 img, int m0, int k0, int lr, int lg) {
  return img + swz(m0 + lr + ((lg & 1) << 3), k0 + ((lg >> 1) << 3));
}
__device__ __forceinline__ u32 b_addr(u32 img, int n0, int k0, int lr, int lg) {
  return img + swz(n0 + lr + ((lg >> 1) << 3), k0 + ((lg & 1) << 3));
}
__device__ __forceinline__ void mma16816(float c[4], const u32 a[4], u32 b0, u32 b1) {
  asm volatile(
    "mma.sync.aligned.m16n8k16.row.col.f32.bf16.bf16.f32 "
    "{%0,%1,%2,%3}, {%4,%5,%6,%7}, {%8,%9}, {%0,%1,%2,%3};"
    : "+f"(c[0]), "+f"(c[1]), "+f"(c[2]), "+f"(c[3])
    : "r"(a[0]), "r"(a[1]), "r"(a[2]), "r"(a[3]), "r"(b0), "r"(b1));
}
__device__ __forceinline__ void cpa16(u32 dst, const void* src) {
  asm volatile("cp.async.cg.shared.global [%0], [%1], 16;" :: "r"(dst), "l"(src));
}
#define CP_COMMIT() asm volatile("cp.async.commit_group;" ::: "memory")
#define CP_WAIT0()  asm volatile("cp.async.wait_group 0;" ::: "memory")

// ============================ threefry dropout ==============================
__device__ __forceinline__ u32 rotl32(u32 x, u32 r) { return __funnelshift_l(x, x, r); }
__device__ __forceinline__ void tf2x32(u32 x0, u32 x1, u32 &o0, u32 &o1) {
  const u32 ks0 = 0u, ks1 = 42u, ks2 = 0u ^ 42u ^ 0x1BD11BDAu;
  x0 += ks0; x1 += ks1;
#define TFR(r) { x0 += x1; x1 = rotl32(x1, r); x1 ^= x0; }
  TFR(13) TFR(15) TFR(26) TFR(6)
  x0 += ks1; x1 += ks2 + 1u;
  TFR(17) TFR(29) TFR(16) TFR(24)
  x0 += ks2; x1 += ks0 + 2u;
  TFR(13) TFR(15) TFR(26) TFR(6)
  x0 += ks0; x1 += ks1 + 3u;
  TFR(17) TFR(29) TFR(16) TFR(24)
  x0 += ks1; x1 += ks2 + 4u;
  TFR(13) TFR(15) TFR(26) TFR(6)
  x0 += ks2; x1 += ks0 + 5u;
#undef TFR
  o0 = x0; o1 = x1;
}
__device__ __forceinline__ bool drop_elem(u32 i) {   // validated rel_err 0.0 (R1)
  u32 o0, o1;
  tf2x32(0u, i, o0, o1);
  u32 bits = o0 ^ o1;
  float u = __uint_as_float((bits >> 9) | 0x3f800000u) - 1.0f;
  return u < 0.2f;
}

// ============================ split helpers =================================
__device__ __forceinline__ void split_pack(float a, float b, u32 &h, u32 &l) {
  __nv_bfloat16 ha = __float2bfloat16(a);
  __nv_bfloat16 hb = __float2bfloat16(b);
  __nv_bfloat16 la = __float2bfloat16(a - __bfloat162float(ha));
  __nv_bfloat16 lb = __float2bfloat16(b - __bfloat162float(hb));
  h = (u32)__bfloat16_as_ushort(ha) | ((u32)__bfloat16_as_ushort(hb) << 16);
  l = (u32)__bfloat16_as_ushort(la) | ((u32)__bfloat16_as_ushort(lb) << 16);
}

// ============================ prep kernel ===================================
__global__ void prep_kernel(const float* __restrict__ W1,
                            const float* __restrict__ W2) {
  int idx = blockIdx.x * blockDim.x + threadIdx.x;
  const int N1 = NCHUNK * KC * K1PAD;
  const int N2 = NCHUNK * EDIM * K1PAD;
  if (idx < N1) {
    int kc = idx / (KC * K1PAD);
    int r  = idx - kc * (KC * K1PAD);
    int n = r / K1PAD, k = r - (r / K1PAD) * K1PAD;
    float w = (k < LSEQ) ? W1[(size_t)k * HDIM + kc * KC + n] : 0.0f;
    __nv_bfloat16 hi = __float2bfloat16(w);
    __nv_bfloat16 lo = __float2bfloat16(w - __bfloat162float(hi));
    u32 sw = swz(n, k);
    *(unsigned short*)&g_w1img[kc][0][sw] = __bfloat16_as_ushort(hi);
    *(unsigned short*)&g_w1img[kc][1][sw] = __bfloat16_as_ushort(lo);
  } else if (idx < N1 + N2) {
    int r2 = idx - N1;
    int kc = r2 / (EDIM * K1PAD);
    int r  = r2 - kc * (EDIM * K1PAD);
    int n = r / K1PAD, k = r - (r / K1PAD) * K1PAD;
    float w = W2[(size_t)(kc * KC + k) * EDIM + n];
    __nv_bfloat16 hi = __float2bfloat16(w);
    __nv_bfloat16 lo = __float2bfloat16(w - __bfloat162float(hi));
    u32 sw = swz(n, k);
    *(unsigned short*)&g_w2img[kc][0][sw] = __bfloat16_as_ushort(hi);
    *(unsigned short*)&g_w2img[kc][1][sw] = __bfloat16_as_ushort(lo);
  }
}

// ============================ main kernel ===================================
extern __shared__ __align__(1024) unsigned char smem_raw[];

__global__ void __launch_bounds__(NTHREADS, 1)
seqfc_main(const float* __restrict__ seq,
           const float* __restrict__ b1,
           const float* __restrict__ b2,
           float* __restrict__ out)
{
  const int tid  = threadIdx.x;
  const int wid  = tid >> 5;
  const int lane = tid & 31;
  const int lr   = lane & 7;
  const int lg   = lane >> 3;
  const int gid  = lane >> 2;
  const int tig  = lane & 3;
  const int wr   = wid >> 1;          // 8 row groups of 16 rows
  const int wc   = wid & 1;           // 2 col groups
  const int row0 = blockIdx.x * MTILE;

  const u32 sm = smem_u32_of(smem_raw);
  float* b1s = (float*)(smem_raw + SM_B1);
  float* b2s = (float*)(smem_raw + SM_B2);

  // ---- prologue: chunk-0 weights via cp.async ----
  {
    u32 d1 = sm + SM_W1;
    const unsigned char* s1 = &g_w1img[0][0][0];          // 16KB
    for (int i = tid; i < 1024; i += NTHREADS) cpa16(d1 + i * 16, s1 + (size_t)i * 16);
    u32 d2 = sm + SM_W2;
    const unsigned char* s2 = &g_w2img[0][0][0];          // 64KB
    for (int i = tid; i < 4096; i += NTHREADS) cpa16(d2 + i * 16, s2 + (size_t)i * 16);
    CP_COMMIT();
  }

  for (int i = tid; i < HDIM; i += NTHREADS) b1s[i] = b1[i];
  for (int i = tid; i < EDIM; i += NTHREADS) b2s[i] = b2[i];

  // ---- X stage: one row per thread (tid < 128) ----
  if (tid < MTILE) {
    const int grow = row0 + tid;
    const float2* xp2 = (const float2*)(seq + (size_t)grow * LSEQ);
    float xv[LSEQ];
#pragma unroll
    for (int i = 0; i < LSEQ / 2; ++i) { float2 t = xp2[i]; xv[2*i] = t.x; xv[2*i+1] = t.y; }
    int f = LSEQ;
#pragma unroll
    for (int l = LSEQ - 1; l >= 0; --l) if (xv[l] == -1.0f) f = l;
    const u32 gbase = (u32)grow * (u32)LSEQ;
#pragma unroll
    for (int l = 0; l < LSEQ; ++l)
      if (l < f && drop_elem(gbase + l)) xv[l] = 0.0f;
#pragma unroll
    for (int c = 0; c < 32; ++c) {
      float a = (2*c   < LSEQ) ? xv[2*c]   : 0.0f;
      float b = (2*c+1 < LSEQ) ? xv[2*c+1] : 0.0f;
      u32 h, l;
      split_pack(a, b, h, l);
      u32 o = swz(tid, 2 * c);
      *(u32*)(smem_raw + SM_XHI + o) = h;
      *(u32*)(smem_raw + SM_XLO + o) = l;
    }
  }

  // ---- GEMM2 accumulators: warp tile = 16 rows x 128 cols ----
  float acc2[16][4];
#pragma unroll
  for (int i = 0; i < 16; ++i)
#pragma unroll
    for (int j = 0; j < 4; ++j) acc2[i][j] = 0.0f;

  // ---- chunk loop ----
  for (int kc = 0; kc < NCHUNK; ++kc) {
    const u32 wb2 = sm + SM_W2 + (u32)(kc & 1) * W2BUFSZ;

    CP_WAIT0();
    __syncthreads();          // W1/W2[kc] ready; X ready (kc=0); h[kc-1] reads done

    // ---- GEMM1: h_chunk[128 x 64] (warp: 16 rows x 32 cols) ----
    float acc1[4][4];
#pragma unroll
    for (int i = 0; i < 4; ++i)
#pragma unroll
      for (int j = 0; j < 4; ++j) acc1[i][j] = 0.0f;

#pragma unroll
    for (int kt = 0; kt < 4; ++kt) {
      const int k0 = kt * 16;
      u32 axh[4], axl[4];
      ldsm4(a_addr(sm + SM_XHI, wr * 16, k0, lr, lg), axh);
      ldsm4(a_addr(sm + SM_XLO, wr * 16, k0, lr, lg), axl);
#pragma unroll
      for (int ntp = 0; ntp < 2; ++ntp) {
        const int n0 = wc * 32 + ntp * 16;
        u32 bh[4], bl[4];
        ldsm4(b_addr(sm + SM_W1,        n0, k0, lr, lg), bh);
        ldsm4(b_addr(sm + SM_W1 + 8192, n0, k0, lr, lg), bl);
        mma16816(acc1[2*ntp],     axh, bh[0], bh[1]);
        mma16816(acc1[2*ntp + 1], axh, bh[2], bh[3]);
        mma16816(acc1[2*ntp],     axl, bh[0], bh[1]);
        mma16816(acc1[2*ntp + 1], axl, bh[2], bh[3]);
        mma16816(acc1[2*ntp],     axh, bl[0], bl[1]);
        mma16816(acc1[2*ntp + 1], axh, bl[2], bl[3]);
      }
    }

    // ---- bias + relu + split -> h images ----
    {
      const int r0 = wr * 16 + gid;
#pragma unroll
      for (int nt = 0; nt < 4; ++nt) {
        const int cc = wc * 32 + nt * 8 + 2 * tig;
        const float bb0 = b1s[kc * KC + cc];
        const float bb1 = b1s[kc * KC + cc + 1];
        float v0 = fmaxf(acc1[nt][0] + bb0, 0.0f);
        float v1 = fmaxf(acc1[nt][1] + bb1, 0.0f);
        float v2 = fmaxf(acc1[nt][2] + bb0, 0.0f);
        float v3 = fmaxf(acc1[nt][3] + bb1, 0.0f);
        u32 h0, l0, h1, l1;
        split_pack(v0, v1, h0, l0);
        split_pack(v2, v3, h1, l1);
        u32 oa = swz(r0, cc), ob = swz(r0 + 8, cc);
        *(u32*)(smem_raw + SM_HHI + oa) = h0;
        *(u32*)(smem_raw + SM_HLO + oa) = l0;
        *(u32*)(smem_raw + SM_HHI + ob) = h1;
        *(u32*)(smem_raw + SM_HLO + ob) = l1;
      }
    }
    __syncthreads();          // h visible; W1 buffer free

    // ---- prefetch next chunk weights (overlaps GEMM2 below) ----
    if (kc + 1 < NCHUNK) {
      u32 d1 = sm + SM_W1;
      const unsigned char* s1 = &g_w1img[kc + 1][0][0];
      for (int i = tid; i < 1024; i += NTHREADS) cpa16(d1 + i * 16, s1 + (size_t)i * 16);
      u32 d2 = sm + SM_W2 + (u32)((kc + 1) & 1) * W2BUFSZ;
      const unsigned char* s2 = &g_w2img[kc + 1][0][0];
      for (int i = tid; i < 4096; i += NTHREADS) cpa16(d2 + i * 16, s2 + (size_t)i * 16);
      CP_COMMIT();
    }

    // ---- GEMM2: acc2 += h_chunk @ W2chunk (warp: 16 rows x 128 cols) ----
#pragma unroll
    for (int kt = 0; kt < 4; ++kt) {
      const int k0 = kt * 16;
      u32 ahh[4], ahl[4];
      ldsm4(a_addr(sm + SM_HHI, wr * 16, k0, lr, lg), ahh);
      ldsm4(a_addr(sm + SM_HLO, wr * 16, k0, lr, lg), ahl);
#pragma unroll
      for (int ntp = 0; ntp < 8; ++ntp) {
        const int n0 = wc * 128 + ntp * 16;
        u32 bh[4], bl[4];
        ldsm4(b_addr(wb2,          n0, k0, lr, lg), bh);
        ldsm4(b_addr(wb2 + 32768u, n0, k0, lr, lg), bl);
        mma16816(acc2[2*ntp],     ahh, bh[0], bh[1]);
        mma16816(acc2[2*ntp + 1], ahh, bh[2], bh[3]);
        mma16816(acc2[2*ntp],     ahl, bh[0], bh[1]);
        mma16816(acc2[2*ntp + 1], ahl, bh[2], bh[3]);
        mma16816(acc2[2*ntp],     ahh, bl[0], bl[1]);
        mma16816(acc2[2*ntp + 1], ahh, bl[2], bl[3]);
      }
    }
  }

  // ---- epilogue: + b2, store ----
  {
    const int r0 = row0 + wr * 16 + gid;
#pragma unroll
    for (int nt = 0; nt < 16; ++nt) {
      const int c = wc * 128 + nt * 8 + 2 * tig;
      const float bb0 = b2s[c], bb1 = b2s[c + 1];
      float2 va = make_float2(acc2[nt][0] + bb0, acc2[nt][1] + bb1);
      float2 vb = make_float2(acc2[nt][2] + bb0, acc2[nt][3] + bb1);
      *(float2*)(out + (size_t)r0 * EDIM + c)       = va;
      *(float2*)(out + (size_t)(r0 + 8) * EDIM + c) = vb;
    }
  }
}

// ============================ launch ========================================
extern "C" void kernel_launch(void* const* d_in, const int* in_sizes, int n_in,
                              void* d_out, int out_size) {
  (void)in_sizes; (void)n_in; (void)out_size;
  const float* seq = (const float*)d_in[0];
  const float* W1  = (const float*)d_in[1];
  const float* b1  = (const float*)d_in[2];
  const float* W2  = (const float*)d_in[3];
  const float* b2  = (const float*)d_in[4];

  cudaFuncSetAttribute(seqfc_main, cudaFuncAttributeMaxDynamicSharedMemorySize,
                       SMEM_TOTAL);

  const int prep_total = NCHUNK * KC * K1PAD + NCHUNK * EDIM * K1PAD;
  prep_kernel<<<(prep_total + 255) / 256, 256>>>(W1, W2);
  seqfc_main<<<B_TOTAL / MTILE, NTHREADS, SMEM_TOTAL>>>(seq, b1, b2, (float*)d_out);
}

// round 5
// speedup vs baseline: 2.5210x; 1.0191x over previous
#include <cuda_runtime.h>
#include <cuda_bf16.h>
#include <stdint.h>

// ---------------------------------------------------------------------------
// SeqFCEncoder via warp-level mma.sync (compute_103 base ISA).
// Split-bf16 3-pass per GEMM: A*B = Ahi*Bhi + Alo*Bhi + Ahi*Blo (fp32 accum).
// R5: warp retile (GEMM2 32x64, GEMM1 32x16) -> -33% LDSM, pass-major MMA
//     ordering for RAW distance 8 on accumulators.
// ---------------------------------------------------------------------------

typedef unsigned int u32;
typedef unsigned long long u64;

#define B_TOTAL   262144
#define LSEQ      50
#define HDIM      1024
#define EDIM      256
#define MTILE     128
#define NTHREADS  512
#define KC        64
#define NCHUNK    (HDIM / KC)     // 16
#define K1PAD     64

// ---- smem layout (bytes, dynamic) ----
#define SM_XHI   0               // 16KB  X hi  [128 m][64 k] SW128
#define SM_XLO   16384           // 16KB
#define SM_HHI   32768           // 16KB  h chunk hi [128 m][64 k] SW128
#define SM_HLO   49152           // 16KB
#define SM_B1    65536           // 4KB
#define SM_B2    69632           // 1KB
#define SM_W1    70656           // 16KB single buffer [hi 8K | lo 8K]
#define SM_W2    87040           // 2 x 64KB double buffer [hi 32K | lo 32K]
#define W2BUFSZ  65536
#define SMEM_TOTAL (SM_W2 + 2 * W2BUFSZ)   // 218112

// ---- pre-split, pre-swizzled weight images (SW128 K-major [n][k=64]) ----
__device__ __align__(1024) unsigned char g_w1img[NCHUNK][2][KC   * K1PAD * 2]; // 256KB
__device__ __align__(1024) unsigned char g_w2img[NCHUNK][2][EDIM * K1PAD * 2]; // 1MB

// ============================ low-level helpers =============================
__device__ __forceinline__ u32 smem_u32_of(const void* p) {
  u32 a;
  asm("{ .reg .u64 t; cvta.to.shared.u64 t, %1; cvt.u32.u64 %0, t; }" : "=r"(a) : "l"(p));
  return a;
}
__device__ __forceinline__ u32 swz(int r, int k) {
  u32 off = ((u32)(r >> 3) << 10) | ((u32)(r & 7) << 7) | ((u32)k << 1);
  return off ^ ((off >> 3) & 0x70u);
}
__device__ __forceinline__ void ldsm4(u32 addr, u32 f[4]) {
  asm volatile("ldmatrix.sync.aligned.m8n8.x4.shared.b16 {%0,%1,%2,%3}, [%4];"
               : "=r"(f[0]), "=r"(f[1]), "=r"(f[2]), "=r"(f[3]) : "r"(addr));
}
__device__ __forceinline__ u32 a_addr(u32 img, int m0, int k0, int lr, int lg) {
  return img + swz(m0 + lr + ((lg & 1) << 3), k0 + ((lg >> 1) << 3));
}
__device__ __forceinline__ u32 b_addr(u32 img, int n0, int k0, int lr, int lg) {
  return img + swz(n0 + lr + ((lg >> 1) << 3), k0 + ((lg & 1) << 3));
}
__device__ __forceinline__ void mma16816(float c[4], const u32 a[4], u32 b0, u32 b1) {
  asm volatile(
    "mma.sync.aligned.m16n8k16.row.col.f32.bf16.bf16.f32 "
    "{%0,%1,%2,%3}, {%4,%5,%6,%7}, {%8,%9}, {%0,%1,%2,%3};"
    : "+f"(c[0]), "+f"(c[1]), "+f"(c[2]), "+f"(c[3])
    : "r"(a[0]), "r"(a[1]), "r"(a[2]), "r"(a[3]), "r"(b0), "r"(b1));
}
__device__ __forceinline__ void cpa16(u32 dst, const void* src) {
  asm volatile("cp.async.cg.shared.global [%0], [%1], 16;" :: "r"(dst), "l"(src));
}
#define CP_COMMIT() asm volatile("cp.async.commit_group;" ::: "memory")
#define CP_WAIT0()  asm volatile("cp.async.wait_group 0;" ::: "memory")

// ============================ threefry dropout ==============================
__device__ __forceinline__ u32 rotl32(u32 x, u32 r) { return __funnelshift_l(x, x, r); }
__device__ __forceinline__ void tf2x32(u32 x0, u32 x1, u32 &o0, u32 &o1) {
  const u32 ks0 = 0u, ks1 = 42u, ks2 = 0u ^ 42u ^ 0x1BD11BDAu;
  x0 += ks0; x1 += ks1;
#define TFR(r) { x0 += x1; x1 = rotl32(x1, r); x1 ^= x0; }
  TFR(13) TFR(15) TFR(26) TFR(6)
  x0 += ks1; x1 += ks2 + 1u;
  TFR(17) TFR(29) TFR(16) TFR(24)
  x0 += ks2; x1 += ks0 + 2u;
  TFR(13) TFR(15) TFR(26) TFR(6)
  x0 += ks0; x1 += ks1 + 3u;
  TFR(17) TFR(29) TFR(16) TFR(24)
  x0 += ks1; x1 += ks2 + 4u;
  TFR(13) TFR(15) TFR(26) TFR(6)
  x0 += ks2; x1 += ks0 + 5u;
#undef TFR
  o0 = x0; o1 = x1;
}
__device__ __forceinline__ bool drop_elem(u32 i) {   // validated rel_err 0.0 (R1)
  u32 o0, o1;
  tf2x32(0u, i, o0, o1);
  u32 bits = o0 ^ o1;
  float u = __uint_as_float((bits >> 9) | 0x3f800000u) - 1.0f;
  return u < 0.2f;
}

// ============================ split helpers =================================
__device__ __forceinline__ void split_pack(float a, float b, u32 &h, u32 &l) {
  __nv_bfloat16 ha = __float2bfloat16(a);
  __nv_bfloat16 hb = __float2bfloat16(b);
  __nv_bfloat16 la = __float2bfloat16(a - __bfloat162float(ha));
  __nv_bfloat16 lb = __float2bfloat16(b - __bfloat162float(hb));
  h = (u32)__bfloat16_as_ushort(ha) | ((u32)__bfloat16_as_ushort(hb) << 16);
  l = (u32)__bfloat16_as_ushort(la) | ((u32)__bfloat16_as_ushort(lb) << 16);
}

// ============================ prep kernel ===================================
__global__ void prep_kernel(const float* __restrict__ W1,
                            const float* __restrict__ W2) {
  int idx = blockIdx.x * blockDim.x + threadIdx.x;
  const int N1 = NCHUNK * KC * K1PAD;
  const int N2 = NCHUNK * EDIM * K1PAD;
  if (idx < N1) {
    int kc = idx / (KC * K1PAD);
    int r  = idx - kc * (KC * K1PAD);
    int n = r / K1PAD, k = r - (r / K1PAD) * K1PAD;
    float w = (k < LSEQ) ? W1[(size_t)k * HDIM + kc * KC + n] : 0.0f;
    __nv_bfloat16 hi = __float2bfloat16(w);
    __nv_bfloat16 lo = __float2bfloat16(w - __bfloat162float(hi));
    u32 sw = swz(n, k);
    *(unsigned short*)&g_w1img[kc][0][sw] = __bfloat16_as_ushort(hi);
    *(unsigned short*)&g_w1img[kc][1][sw] = __bfloat16_as_ushort(lo);
  } else if (idx < N1 + N2) {
    int r2 = idx - N1;
    int kc = r2 / (EDIM * K1PAD);
    int r  = r2 - kc * (EDIM * K1PAD);
    int n = r / K1PAD, k = r - (r / K1PAD) * K1PAD;
    float w = W2[(size_t)(kc * KC + k) * EDIM + n];
    __nv_bfloat16 hi = __float2bfloat16(w);
    __nv_bfloat16 lo = __float2bfloat16(w - __bfloat162float(hi));
    u32 sw = swz(n, k);
    *(unsigned short*)&g_w2img[kc][0][sw] = __bfloat16_as_ushort(hi);
    *(unsigned short*)&g_w2img[kc][1][sw] = __bfloat16_as_ushort(lo);
  }
}

// ============================ main kernel ===================================
extern __shared__ __align__(1024) unsigned char smem_raw[];

__global__ void __launch_bounds__(NTHREADS, 1)
seqfc_main(const float* __restrict__ seq,
           const float* __restrict__ b1,
           const float* __restrict__ b2,
           float* __restrict__ out)
{
  const int tid  = threadIdx.x;
  const int wid  = tid >> 5;
  const int lane = tid & 31;
  const int lr   = lane & 7;
  const int lg   = lane >> 3;
  const int gid  = lane >> 2;
  const int tig  = lane & 3;
  const int wr   = wid >> 2;          // 4 row groups of 32 rows
  const int wc   = wid & 3;           // 4 col groups
  const int row0 = blockIdx.x * MTILE;

  const u32 sm = smem_u32_of(smem_raw);
  float* b1s = (float*)(smem_raw + SM_B1);
  float* b2s = (float*)(smem_raw + SM_B2);

  // ---- prologue: chunk-0 weights via cp.async ----
  {
    u32 d1 = sm + SM_W1;
    const unsigned char* s1 = &g_w1img[0][0][0];          // 16KB
    for (int i = tid; i < 1024; i += NTHREADS) cpa16(d1 + i * 16, s1 + (size_t)i * 16);
    u32 d2 = sm + SM_W2;
    const unsigned char* s2 = &g_w2img[0][0][0];          // 64KB
    for (int i = tid; i < 4096; i += NTHREADS) cpa16(d2 + i * 16, s2 + (size_t)i * 16);
    CP_COMMIT();
  }

  for (int i = tid; i < HDIM; i += NTHREADS) b1s[i] = b1[i];
  for (int i = tid; i < EDIM; i += NTHREADS) b2s[i] = b2[i];

  // ---- X stage: one row per thread (tid < 128) ----
  if (tid < MTILE) {
    const int grow = row0 + tid;
    const float2* xp2 = (const float2*)(seq + (size_t)grow * LSEQ);
    float xv[LSEQ];
#pragma unroll
    for (int i = 0; i < LSEQ / 2; ++i) { float2 t = xp2[i]; xv[2*i] = t.x; xv[2*i+1] = t.y; }
    int f = LSEQ;
#pragma unroll
    for (int l = LSEQ - 1; l >= 0; --l) if (xv[l] == -1.0f) f = l;
    const u32 gbase = (u32)grow * (u32)LSEQ;
#pragma unroll
    for (int l = 0; l < LSEQ; ++l)
      if (l < f && drop_elem(gbase + l)) xv[l] = 0.0f;
#pragma unroll
    for (int c = 0; c < 32; ++c) {
      float a = (2*c   < LSEQ) ? xv[2*c]   : 0.0f;
      float b = (2*c+1 < LSEQ) ? xv[2*c+1] : 0.0f;
      u32 h, l;
      split_pack(a, b, h, l);
      u32 o = swz(tid, 2 * c);
      *(u32*)(smem_raw + SM_XHI + o) = h;
      *(u32*)(smem_raw + SM_XLO + o) = l;
    }
  }

  // ---- GEMM2 accumulators: warp tile = 32 rows x 64 cols ----
  // acc2[mt][j]: rows wr*32 + mt*16, cols wc*64 + j*8
  float acc2[2][8][4];
#pragma unroll
  for (int mt = 0; mt < 2; ++mt)
#pragma unroll
    for (int j = 0; j < 8; ++j)
#pragma unroll
      for (int q = 0; q < 4; ++q) acc2[mt][j][q] = 0.0f;

  // ---- chunk loop ----
  for (int kc = 0; kc < NCHUNK; ++kc) {
    const u32 wb2 = sm + SM_W2 + (u32)(kc & 1) * W2BUFSZ;

    CP_WAIT0();
    __syncthreads();          // W1/W2[kc] ready; X ready (kc=0); h[kc-1] reads done

    // ---- GEMM1: h_chunk[128 x 64], warp tile 32 rows x 16 cols ----
    // acc1[mt][j]: rows wr*32 + mt*16, cols wc*16 + j*8
    float acc1[2][2][4];
#pragma unroll
    for (int mt = 0; mt < 2; ++mt)
#pragma unroll
      for (int j = 0; j < 2; ++j)
#pragma unroll
        for (int q = 0; q < 4; ++q) acc1[mt][j][q] = 0.0f;

#pragma unroll
    for (int kt = 0; kt < 4; ++kt) {
      const int k0 = kt * 16;
      u32 axh[2][4], axl[2][4];
      ldsm4(a_addr(sm + SM_XHI, wr * 32,      k0, lr, lg), axh[0]);
      ldsm4(a_addr(sm + SM_XHI, wr * 32 + 16, k0, lr, lg), axh[1]);
      ldsm4(a_addr(sm + SM_XLO, wr * 32,      k0, lr, lg), axl[0]);
      ldsm4(a_addr(sm + SM_XLO, wr * 32 + 16, k0, lr, lg), axl[1]);
      u32 bh[4], bl[4];
      const int n0 = wc * 16;
      ldsm4(b_addr(sm + SM_W1,        n0, k0, lr, lg), bh);
      ldsm4(b_addr(sm + SM_W1 + 8192, n0, k0, lr, lg), bl);
      // pass-major: 4 distinct accumulators between same-acc writes
      mma16816(acc1[0][0], axh[0], bh[0], bh[1]);
      mma16816(acc1[0][1], axh[0], bh[2], bh[3]);
      mma16816(acc1[1][0], axh[1], bh[0], bh[1]);
      mma16816(acc1[1][1], axh[1], bh[2], bh[3]);
      mma16816(acc1[0][0], axl[0], bh[0], bh[1]);
      mma16816(acc1[0][1], axl[0], bh[2], bh[3]);
      mma16816(acc1[1][0], axl[1], bh[0], bh[1]);
      mma16816(acc1[1][1], axl[1], bh[2], bh[3]);
      mma16816(acc1[0][0], axh[0], bl[0], bl[1]);
      mma16816(acc1[0][1], axh[0], bl[2], bl[3]);
      mma16816(acc1[1][0], axh[1], bl[0], bl[1]);
      mma16816(acc1[1][1], axh[1], bl[2], bl[3]);
    }

    // ---- bias + relu + split -> h images ----
#pragma unroll
    for (int mt = 0; mt < 2; ++mt) {
      const int r0 = wr * 32 + mt * 16 + gid;
#pragma unroll
      for (int j = 0; j < 2; ++j) {
        const int cc = wc * 16 + j * 8 + 2 * tig;
        const float bb0 = b1s[kc * KC + cc];
        const float bb1 = b1s[kc * KC + cc + 1];
        float v0 = fmaxf(acc1[mt][j][0] + bb0, 0.0f);
        float v1 = fmaxf(acc1[mt][j][1] + bb1, 0.0f);
        float v2 = fmaxf(acc1[mt][j][2] + bb0, 0.0f);
        float v3 = fmaxf(acc1[mt][j][3] + bb1, 0.0f);
        u32 h0, l0, h1, l1;
        split_pack(v0, v1, h0, l0);
        split_pack(v2, v3, h1, l1);
        u32 oa = swz(r0, cc), ob = swz(r0 + 8, cc);
        *(u32*)(smem_raw + SM_HHI + oa) = h0;
        *(u32*)(smem_raw + SM_HLO + oa) = l0;
        *(u32*)(smem_raw + SM_HHI + ob) = h1;
        *(u32*)(smem_raw + SM_HLO + ob) = l1;
      }
    }
    __syncthreads();          // h visible; W1 buffer free

    // ---- prefetch next chunk weights (overlaps GEMM2 below) ----
    if (kc + 1 < NCHUNK) {
      u32 d1 = sm + SM_W1;
      const unsigned char* s1 = &g_w1img[kc + 1][0][0];
      for (int i = tid; i < 1024; i += NTHREADS) cpa16(d1 + i * 16, s1 + (size_t)i * 16);
      u32 d2 = sm + SM_W2 + (u32)((kc + 1) & 1) * W2BUFSZ;
      const unsigned char* s2 = &g_w2img[kc + 1][0][0];
      for (int i = tid; i < 4096; i += NTHREADS) cpa16(d2 + i * 16, s2 + (size_t)i * 16);
      CP_COMMIT();
    }

    // ---- GEMM2: acc2 += h_chunk @ W2chunk (warp tile 32 rows x 64 cols) ----
#pragma unroll
    for (int kt = 0; kt < 4; ++kt) {
      const int k0 = kt * 16;
      u32 ahh[2][4], ahl[2][4];
      ldsm4(a_addr(sm + SM_HHI, wr * 32,      k0, lr, lg), ahh[0]);
      ldsm4(a_addr(sm + SM_HHI, wr * 32 + 16, k0, lr, lg), ahh[1]);
      ldsm4(a_addr(sm + SM_HLO, wr * 32,      k0, lr, lg), ahl[0]);
      ldsm4(a_addr(sm + SM_HLO, wr * 32 + 16, k0, lr, lg), ahl[1]);
#pragma unroll
      for (int half = 0; half < 2; ++half) {
        // two n16-tiles per half: nt = half*2, half*2+1
        u32 b2h[2][4], b2l[2][4];
#pragma unroll
        for (int t = 0; t < 2; ++t) {
          const int n0 = wc * 64 + (half * 2 + t) * 16;
          ldsm4(b_addr(wb2,          n0, k0, lr, lg), b2h[t]);
          ldsm4(b_addr(wb2 + 32768u, n0, k0, lr, lg), b2l[t]);
        }
        const int jb = half * 4;
        // pass 0: Ahi * Bhi  (8 distinct accumulators)
#pragma unroll
        for (int t = 0; t < 2; ++t) {
          mma16816(acc2[0][jb + 2*t],     ahh[0], b2h[t][0], b2h[t][1]);
          mma16816(acc2[0][jb + 2*t + 1], ahh[0], b2h[t][2], b2h[t][3]);
          mma16816(acc2[1][jb + 2*t],     ahh[1], b2h[t][0], b2h[t][1]);
          mma16816(acc2[1][jb + 2*t + 1], ahh[1], b2h[t][2], b2h[t][3]);
        }
        // pass 1: Alo * Bhi
#pragma unroll
        for (int t = 0; t < 2; ++t) {
          mma16816(acc2[0][jb + 2*t],     ahl[0], b2h[t][0], b2h[t][1]);
          mma16816(acc2[0][jb + 2*t + 1], ahl[0], b2h[t][2], b2h[t][3]);
          mma16816(acc2[1][jb + 2*t],     ahl[1], b2h[t][0], b2h[t][1]);
          mma16816(acc2[1][jb + 2*t + 1], ahl[1], b2h[t][2], b2h[t][3]);
        }
        // pass 2: Ahi * Blo
#pragma unroll
        for (int t = 0; t < 2; ++t) {
          mma16816(acc2[0][jb + 2*t],     ahh[0], b2l[t][0], b2l[t][1]);
          mma16816(acc2[0][jb + 2*t + 1], ahh[0], b2l[t][2], b2l[t][3]);
          mma16816(acc2[1][jb + 2*t],     ahh[1], b2l[t][0], b2l[t][1]);
          mma16816(acc2[1][jb + 2*t + 1], ahh[1], b2l[t][2], b2l[t][3]);
        }
      }
    }
  }

  // ---- epilogue: + b2, store ----
#pragma unroll
  for (int mt = 0; mt < 2; ++mt) {
    const int r0 = row0 + wr * 32 + mt * 16 + gid;
#pragma unroll
    for (int j = 0; j < 8; ++j) {
      const int c = wc * 64 + j * 8 + 2 * tig;
      const float bb0 = b2s[c], bb1 = b2s[c + 1];
      float2 va = make_float2(acc2[mt][j][0] + bb0, acc2[mt][j][1] + bb1);
      float2 vb = make_float2(acc2[mt][j][2] + bb0, acc2[mt][j][3] + bb1);
      *(float2*)(out + (size_t)r0 * EDIM + c)       = va;
      *(float2*)(out + (size_t)(r0 + 8) * EDIM + c) = vb;
    }
  }
}

// ============================ launch ========================================
extern "C" void kernel_launch(void* const* d_in, const int* in_sizes, int n_in,
                              void* d_out, int out_size) {
  (void)in_sizes; (void)n_in; (void)out_size;
  const float* seq = (const float*)d_in[0];
  const float* W1  = (const float*)d_in[1];
  const float* b1  = (const float*)d_in[2];
  const float* W2  = (const float*)d_in[3];
  const float* b2  = (const float*)d_in[4];

  cudaFuncSetAttribute(seqfc_main, cudaFuncAttributeMaxDynamicSharedMemorySize,
                       SMEM_TOTAL);

  const int prep_total = NCHUNK * KC * K1PAD + NCHUNK * EDIM * K1PAD;
  prep_kernel<<<(prep_total + 255) / 256, 256>>>(W1, W2);
  seqfc_main<<<B_TOTAL / MTILE, NTHREADS, SMEM_TOTAL>>>(seq, b1, b2, (float*)d_out);
}